// round 7
// baseline (speedup 1.0000x reference)
#include <cuda_runtime.h>
#include <math.h>

#define BB 4
#define CC 7
#define HH 512
#define WW 1024
#define HW (HH*WW)            // 524288
#define NID 7
#define NTASK (BB*NID)        // 28
#define NBINS 2048            // e-bins over [0,2]
#define FULLM 0xffffffffu

// ---- persistent scratch ----
__device__ float4   g_pack[BB*HW];            // ex, ey, seed, inst(bits)
__device__ unsigned g_hist[NTASK*NBINS*2];    // [task][bin*2 + fg]
__device__ float    g_stat[NTASK*7];          // cnt, sum_xw, sum_yh, s0, s1, s0^2, s1^2
__device__ float    g_batch[BB*3];            // cls_sum, valid_cnt, seed_bg
__device__ float    g_task[NTASK*8];          // cx, cy, sex, sey, varl, present
__device__ float    g_seedfg[NTASK];
__device__ float    g_instl[NTASK];

// ---------------- zero accumulators ----------------
__global__ __launch_bounds__(256) void zeroK() {
    int i = blockIdx.x*blockDim.x + threadIdx.x;
    int stride = gridDim.x*blockDim.x;
    uint4* h4 = (uint4*)g_hist;
    const int n4 = NTASK*NBINS*2/4;
    uint4 z = make_uint4(0u,0u,0u,0u);
    for (int j = i; j < n4; j += stride) h4[j] = z;
    if (blockIdx.x == 0) {
        if (threadIdx.x < NTASK*7) g_stat[threadIdx.x]=0.f;
        if (threadIdx.x < BB*3)    g_batch[threadIdx.x]=0.f;
        if (threadIdx.x < NTASK)   g_seedfg[threadIdx.x]=0.f;
    }
}

// ---------------- stage A: per-pixel transforms + per-(b,id) stats ----------------
// Labeled-partition REDUX aggregation: one match on the 8-valued id, hardware
// integer REDUX on fixed-point values, leader-only shared atomics (ATOMS /4.6).
__global__ __launch_bounds__(256) void stageA(const float* __restrict__ pred,
                                              const int*  __restrict__ inst,
                                              const int*  __restrict__ lab) {
    __shared__ float s_acc[52];   // 7 ids * 7 stats + cls, vcnt, seedbg
    int b = blockIdx.y;
    int tid = threadIdx.x;
    int lane = tid & 31;
    if (tid < 52) s_acc[tid] = 0.f;
    __syncthreads();

    const float* pb = pred + b*(CC*HW);
    int base = blockIdx.x*2048;
    float cls = 0.f, vc = 0.f, sbg = 0.f;

    #pragma unroll
    for (int k = 0; k < 8; k++) {
        int pix = base + k*256 + tid;
        float p0 = pb[pix],      p1 = pb[HW+pix],   p2 = pb[2*HW+pix];
        float p3 = pb[3*HW+pix], p4 = pb[4*HW+pix];
        float p5 = pb[5*HW+pix], p6 = pb[6*HW+pix];
        int iv = inst[b*HW+pix];
        int lv = lab [b*HW+pix];
        int w = pix & (WW-1);
        int h = pix >> 10;

        float xw = (2.0f/2047.0f)*(float)w;
        float yh = (1.0f/1023.0f)*(float)h;
        float t0 = __expf(2.f*p0);
        float t1 = __expf(2.f*p1);
        float ex = __fdividef(t0-1.f, t0+1.f) + xw;   // tanh(p0)+xw
        float ey = __fdividef(t1-1.f, t1+1.f) + yh;
        float sd = __fdividef(1.f, 1.f + __expf(-p4));
        float4 P; P.x = ex; P.y = ey; P.z = sd; P.w = __int_as_float(iv);
        g_pack[b*HW+pix] = P;

        if (lv < 2) {
            float m   = fmaxf(p5, p6);
            float lse = m + __logf(__expf(p5-m) + __expf(p6-m));
            float logpt = ((lv == 0) ? p5 : p6) - lse;
            float pt  = __expf(logpt);
            float om  = 1.0f - pt;
            cls -= om*om*logpt;
            vc  += 1.0f;
        }
        if (lv == 0) sbg += sd*sd;

        // partition warp by id; aggregate sums in fixed-point via REDUX
        unsigned grp = __match_any_sync(FULLM, iv);
        if (iv >= 1) {
            int r1 = __reduce_add_sync(grp, __float2int_rn(xw   *1048576.f)); // 2^20
            int r2 = __reduce_add_sync(grp, __float2int_rn(yh   *1048576.f));
            int r3 = __reduce_add_sync(grp, __float2int_rn(p2   * 262144.f)); // 2^18
            int r4 = __reduce_add_sync(grp, __float2int_rn(p3   * 262144.f));
            int r5 = __reduce_add_sync(grp, __float2int_rn(p2*p2*  16384.f)); // 2^14
            int r6 = __reduce_add_sync(grp, __float2int_rn(p3*p3*  16384.f));
            if (lane == __ffs(grp)-1) {
                float* a = &s_acc[(iv-1)*7];
                atomicAdd(a+0, (float)__popc(grp));
                atomicAdd(a+1, (float)r1 * (1.f/1048576.f));
                atomicAdd(a+2, (float)r2 * (1.f/1048576.f));
                atomicAdd(a+3, (float)r3 * (1.f/262144.f));
                atomicAdd(a+4, (float)r4 * (1.f/262144.f));
                atomicAdd(a+5, (float)r5 * (1.f/16384.f));
                atomicAdd(a+6, (float)r6 * (1.f/16384.f));
            }
        }
    }
    // warp-reduce scalars
    #pragma unroll
    for (int o = 16; o; o >>= 1) {
        cls += __shfl_down_sync(FULLM, cls, o);
        vc  += __shfl_down_sync(FULLM, vc,  o);
        sbg += __shfl_down_sync(FULLM, sbg, o);
    }
    if (lane == 0) {
        atomicAdd(&s_acc[49], cls);
        atomicAdd(&s_acc[50], vc);
        atomicAdd(&s_acc[51], sbg);
    }
    __syncthreads();
    if      (tid < 49) atomicAdd(&g_stat[b*49 + tid], s_acc[tid]);
    else if (tid < 52) atomicAdd(&g_batch[b*3 + tid - 49], s_acc[tid]);
}

// ---------------- stage B: per-task derived params ----------------
__global__ void stageB() {
    int t = threadIdx.x;
    if (t >= NTASK) return;
    const float* s = &g_stat[t*7];
    float cnt  = s[0];
    float pres = (cnt > 0.f) ? 1.f : 0.f;
    float cf   = fmaxf(cnt, 1.f);
    float cx = s[1]/cf, cy = s[2]/cf;
    float m0 = s[3]/cf, m1 = s[4]/cf;
    float varl = (s[5] - cnt*m0*m0 + s[6] - cnt*m1*m1) / (2.f*cf);
    g_task[t*8+0] = cx;
    g_task[t*8+1] = cy;
    g_task[t*8+2] = expf(10.f*m0);
    g_task[t*8+3] = expf(10.f*m1);
    g_task[t*8+4] = varl;
    g_task[t*8+5] = pres;
}

// ---------------- stage C: one (b,id) per block, match-aggregated REDs ----------------
__global__ __launch_bounds__(256) void stageC() {
    int b  = blockIdx.y;
    int t  = b*NID + blockIdx.z;
    int id = blockIdx.z + 1;
    if (__ldg(&g_task[t*8+5]) == 0.f) return;   // absent id (uniform)
    float cx = __ldg(&g_task[t*8+0]);
    float cy = __ldg(&g_task[t*8+1]);
    float sx = __ldg(&g_task[t*8+2]);
    float sy = __ldg(&g_task[t*8+3]);
    unsigned* __restrict__ hb = g_hist + t*(NBINS*2);

    const float4* __restrict__ pk = g_pack + b*HW + blockIdx.x*2048 + threadIdx.x;
    int lane = threadIdx.x & 31;
    float sfg = 0.f;

    #pragma unroll
    for (int k = 0; k < 8; k++) {
        float4 P = pk[k*256];
        int iv = __float_as_int(P.w);
        float dx = P.x - cx, dy = P.y - cy;
        float d  = __expf(-(dx*dx*sx + dy*dy*sy));   // d in (0,1]
        bool fg  = (iv == id);
        // e-bin: bg e=2d -> floor(d*N); fg e=2(1-d) -> floor((1-d)*N)
        float v  = fg ? (1.f - d) : d;
        int bin  = min((int)(v * (float)NBINS), NBINS-1);
        unsigned key = ((unsigned)bin << 1) | (fg ? 1u : 0u);
        unsigned same = __match_any_sync(FULLM, key);
        if (lane == __ffs(same)-1)
            atomicAdd(hb + key, (unsigned)__popc(same));
        if (fg) { float df = P.z - d; sfg += df*df; }
    }
    // block-reduce sfg
    #pragma unroll
    for (int o = 16; o; o >>= 1) sfg += __shfl_down_sync(FULLM, sfg, o);
    __shared__ float sred[8];
    if (lane == 0) sred[threadIdx.x >> 5] = sfg;
    __syncthreads();
    if (threadIdx.x == 0) {
        float s = 0.f;
        #pragma unroll
        for (int w = 0; w < 8; w++) s += sred[w];
        atomicAdd(&g_seedfg[t], s);
    }
}

// ---------------- stage D: Lovász via descending-bin scan (fp32) ----------------
__global__ __launch_bounds__(256) void stageD() {
    int t = blockIdx.x;
    if (g_task[t*8+5] == 0.f) { if (threadIdx.x == 0) g_instl[t] = 0.f; return; }
    const uint2* hh = (const uint2*)(g_hist + t*(NBINS*2));   // .x=bg .y=fg
    int tid = threadIdx.x;
    const int BPT = NBINS/256;    // 8 bins/thread, contiguous descending chunk
    int hi = NBINS-1 - tid*BPT;

    // pass 1: chunk sums
    unsigned lf = 0, lt = 0;
    #pragma unroll
    for (int j = 0; j < BPT; j++) {
        uint2 c = hh[hi - j];
        lf += c.y; lt += c.x + c.y;
    }

    // block exclusive scan of (lf, lt): 8 warps
    __shared__ unsigned sWF[8], sWT[8];
    int lane = tid & 31, warp = tid >> 5;
    unsigned incF = lf, incT = lt;
    #pragma unroll
    for (int o = 1; o < 32; o <<= 1) {
        unsigned vF = __shfl_up_sync(FULLM, incF, o);
        unsigned vT = __shfl_up_sync(FULLM, incT, o);
        if (lane >= o) { incF += vF; incT += vT; }
    }
    if (lane == 31) { sWF[warp] = incF; sWT[warp] = incT; }
    __syncthreads();
    if (warp == 0 && lane < 8) {
        unsigned aF = sWF[lane], aT = sWT[lane];
        #pragma unroll
        for (int o = 1; o < 8; o <<= 1) {
            unsigned vF = __shfl_up_sync(0xffu, aF, o);
            unsigned vT = __shfl_up_sync(0xffu, aT, o);
            if (lane >= o) { aF += vF; aT += vT; }
        }
        sWF[lane] = aF; sWT[lane] = aT;
    }
    __syncthreads();
    unsigned F = (warp ? sWF[warp-1] : 0u) + incF - lf;
    unsigned T = (warp ? sWT[warp-1] : 0u) + incT - lt;

    float G = (float)sWF[7];      // exact fg total (< 2^24)
    float jprev = 1.f - (G - (float)F) / (G + (float)(T - F));
    float loss = 0.f;
    #pragma unroll
    for (int j = 0; j < BPT; j++) {
        int bin = hi - j;
        uint2 cc = hh[bin];
        unsigned a = cc.y, c = cc.x + cc.y;
        if (c) {
            F += a; T += c;
            float jnew = 1.f - (G - (float)F) / (G + (float)(T - F));
            float e = ((float)bin + 0.5f) * (2.0f/(float)NBINS);
            loss += e * (jnew - jprev);
            jprev = jnew;
        }
    }
    // block reduce loss
    #pragma unroll
    for (int o = 16; o; o >>= 1) loss += __shfl_down_sync(FULLM, loss, o);
    __shared__ float sL[8];
    if (lane == 0) sL[warp] = loss;
    __syncthreads();
    if (tid == 0) {
        float v = 0.f;
        #pragma unroll
        for (int w = 0; w < 8; w++) v += sL[w];
        g_instl[t] = v;
    }
}

// ---------------- final combine ----------------
__global__ void combineK(float* __restrict__ out) {
    if (threadIdx.x != 0) return;
    float total = 0.f;
    for (int b = 0; b < BB; b++) {
        float ps = 0.f, il = 0.f, vl = 0.f, sf = 0.f;
        for (int i = 0; i < NID; i++) {
            int t = b*NID + i;
            float p = g_task[t*8+5];
            ps += p;
            il += g_instl[t]    * p;
            vl += g_task[t*8+4] * p;
            sf += g_seedfg[t]   * p;
        }
        float obj = fmaxf(ps, 1.f);
        float seed_loss = (g_batch[b*3+2] + 200.f*sf) / (float)HW;
        float loss_b = il/obj + 10.f*(vl/obj) + seed_loss;
        float cls_b  = g_batch[b*3+0] / fmaxf(g_batch[b*3+1], 1.f);
        total += loss_b + cls_b;
    }
    out[0] = total * 0.25f;
}

extern "C" void kernel_launch(void* const* d_in, const int* in_sizes, int n_in,
                              void* d_out, int out_size) {
    const float* pred = (const float*)d_in[0];
    const int*   inst = (const int*)  d_in[1];
    const int*   lab  = (const int*)  d_in[2];
    float* out = (float*)d_out;

    zeroK   <<<128, 256>>>();
    stageA  <<<dim3(HW/2048, BB), 256>>>(pred, inst, lab);
    stageB  <<<1, 32>>>();
    stageC  <<<dim3(HW/2048, BB, NID), 256>>>();
    stageD  <<<NTASK, 256>>>();
    combineK<<<1, 32>>>(out);
}

// round 9
// speedup vs baseline: 1.7312x; 1.7312x over previous
#include <cuda_runtime.h>
#include <math.h>

#define BB 4
#define CC 7
#define HH 512
#define WW 1024
#define HW (HH*WW)            // 524288
#define NID 7
#define NTASK (BB*NID)        // 28
#define NBINS 2048            // e-bins over [0,2]
#define FULLM 0xffffffffu

// ---- persistent scratch ----
__device__ float4   g_pack[BB*HW];            // ex, ey, seed, inst(bits)
__device__ unsigned g_hist[NTASK*NBINS*2];    // [task][bin*2 + fg]  (448 KB, L2-resident)
__device__ float    g_stat[NTASK*7];          // cnt, sum_xw, sum_yh, s0, s1, s0^2, s1^2
__device__ float    g_batch[BB*3];            // cls_sum, valid_cnt, seed_bg
__device__ float    g_task[NTASK*8];          // cx, cy, sex, sey, varl, present
__device__ float    g_seedfg[NTASK];
__device__ float    g_instl[NTASK];

// ---------------- zero accumulators ----------------
__global__ __launch_bounds__(256) void zeroK() {
    int i = blockIdx.x*blockDim.x + threadIdx.x;
    int stride = gridDim.x*blockDim.x;
    uint4* h4 = (uint4*)g_hist;
    const int n4 = NTASK*NBINS*2/4;
    uint4 z = make_uint4(0u,0u,0u,0u);
    for (int j = i; j < n4; j += stride) h4[j] = z;
    if (blockIdx.x == 0) {
        if (threadIdx.x < NTASK*7) g_stat[threadIdx.x]=0.f;
        if (threadIdx.x < BB*3)    g_batch[threadIdx.x]=0.f;
        if (threadIdx.x < NTASK)   g_seedfg[threadIdx.x]=0.f;
    }
}

// ---------------- stage A: per-pixel transforms + per-(b,id) stats ----------------
// Labeled-partition REDUX aggregation: one match on the 8-valued id, hardware
// integer REDUX on fixed-point values, leader-only shared atomics.
__global__ __launch_bounds__(256) void stageA(const float* __restrict__ pred,
                                              const int*  __restrict__ inst,
                                              const int*  __restrict__ lab) {
    __shared__ float s_acc[52];   // 7 ids * 7 stats + cls, vcnt, seedbg
    int b = blockIdx.y;
    int tid = threadIdx.x;
    int lane = tid & 31;
    if (tid < 52) s_acc[tid] = 0.f;
    __syncthreads();

    const float* pb = pred + b*(CC*HW);
    int base = blockIdx.x*2048;
    float cls = 0.f, vc = 0.f, sbg = 0.f;

    #pragma unroll
    for (int k = 0; k < 8; k++) {
        int pix = base + k*256 + tid;
        float p0 = pb[pix],      p1 = pb[HW+pix],   p2 = pb[2*HW+pix];
        float p3 = pb[3*HW+pix], p4 = pb[4*HW+pix];
        float p5 = pb[5*HW+pix], p6 = pb[6*HW+pix];
        int iv = inst[b*HW+pix];
        int lv = lab [b*HW+pix];
        int w = pix & (WW-1);
        int h = pix >> 10;

        float xw = (2.0f/2047.0f)*(float)w;
        float yh = (1.0f/1023.0f)*(float)h;
        float t0 = __expf(2.f*p0);
        float t1 = __expf(2.f*p1);
        float ex = __fdividef(t0-1.f, t0+1.f) + xw;   // tanh(p0)+xw
        float ey = __fdividef(t1-1.f, t1+1.f) + yh;
        float sd = __fdividef(1.f, 1.f + __expf(-p4));
        float4 P; P.x = ex; P.y = ey; P.z = sd; P.w = __int_as_float(iv);
        g_pack[b*HW+pix] = P;

        if (lv < 2) {
            float m   = fmaxf(p5, p6);
            float lse = m + __logf(__expf(p5-m) + __expf(p6-m));
            float logpt = ((lv == 0) ? p5 : p6) - lse;
            float pt  = __expf(logpt);
            float om  = 1.0f - pt;
            cls -= om*om*logpt;
            vc  += 1.0f;
        }
        if (lv == 0) sbg += sd*sd;

        // partition warp by id; aggregate sums in fixed-point via REDUX
        unsigned grp = __match_any_sync(FULLM, iv);
        if (iv >= 1) {
            int r1 = __reduce_add_sync(grp, __float2int_rn(xw   *1048576.f)); // 2^20
            int r2 = __reduce_add_sync(grp, __float2int_rn(yh   *1048576.f));
            int r3 = __reduce_add_sync(grp, __float2int_rn(p2   * 262144.f)); // 2^18
            int r4 = __reduce_add_sync(grp, __float2int_rn(p3   * 262144.f));
            int r5 = __reduce_add_sync(grp, __float2int_rn(p2*p2*  16384.f)); // 2^14
            int r6 = __reduce_add_sync(grp, __float2int_rn(p3*p3*  16384.f));
            if (lane == __ffs(grp)-1) {
                float* a = &s_acc[(iv-1)*7];
                atomicAdd(a+0, (float)__popc(grp));
                atomicAdd(a+1, (float)r1 * (1.f/1048576.f));
                atomicAdd(a+2, (float)r2 * (1.f/1048576.f));
                atomicAdd(a+3, (float)r3 * (1.f/262144.f));
                atomicAdd(a+4, (float)r4 * (1.f/262144.f));
                atomicAdd(a+5, (float)r5 * (1.f/16384.f));
                atomicAdd(a+6, (float)r6 * (1.f/16384.f));
            }
        }
    }
    // warp-reduce scalars
    #pragma unroll
    for (int o = 16; o; o >>= 1) {
        cls += __shfl_down_sync(FULLM, cls, o);
        vc  += __shfl_down_sync(FULLM, vc,  o);
        sbg += __shfl_down_sync(FULLM, sbg, o);
    }
    if (lane == 0) {
        atomicAdd(&s_acc[49], cls);
        atomicAdd(&s_acc[50], vc);
        atomicAdd(&s_acc[51], sbg);
    }
    __syncthreads();
    if      (tid < 49) atomicAdd(&g_stat[b*49 + tid], s_acc[tid]);
    else if (tid < 52) atomicAdd(&g_batch[b*3 + tid - 49], s_acc[tid]);
}

// ---------------- stage B: per-task derived params ----------------
__global__ void stageB() {
    int t = threadIdx.x;
    if (t >= NTASK) return;
    const float* s = &g_stat[t*7];
    float cnt  = s[0];
    float pres = (cnt > 0.f) ? 1.f : 0.f;
    float cf   = fmaxf(cnt, 1.f);
    float cx = s[1]/cf, cy = s[2]/cf;
    float m0 = s[3]/cf, m1 = s[4]/cf;
    float varl = (s[5] - cnt*m0*m0 + s[6] - cnt*m1*m1) / (2.f*cf);
    g_task[t*8+0] = cx;
    g_task[t*8+1] = cy;
    g_task[t*8+2] = expf(10.f*m0);
    g_task[t*8+3] = expf(10.f*m1);
    g_task[t*8+4] = varl;
    g_task[t*8+5] = pres;
}

// ---------------- stage C: all 7 ids per block (ILP), straight REDs ----------------
__global__ __launch_bounds__(256) void stageC() {
    int b = blockIdx.y;
    __shared__ float4 sparam[NID];
    if (threadIdx.x < NID) {
        const float* tk = &g_task[(b*NID+threadIdx.x)*8];
        sparam[threadIdx.x] = make_float4(tk[0], tk[1], tk[2], tk[3]);
    }
    __syncthreads();
    float cx[NID], cy[NID], sx[NID], sy[NID];
    #pragma unroll
    for (int i = 0; i < NID; i++) {
        float4 q = sparam[i];
        cx[i]=q.x; cy[i]=q.y; sx[i]=q.z; sy[i]=q.w;
    }
    unsigned* hb = g_hist + b*NID*NBINS*2;
    float sfg[NID] = {0.f,0.f,0.f,0.f,0.f,0.f,0.f};
    const float4* pk = g_pack + b*HW + blockIdx.x*2048 + threadIdx.x;

    #pragma unroll
    for (int k = 0; k < 8; k++) {
        float4 P = pk[k*256];
        int iv = __float_as_int(P.w);
        #pragma unroll
        for (int i = 0; i < NID; i++) {
            float dx = P.x - cx[i], dy = P.y - cy[i];
            float d  = __expf(-(dx*dx*sx[i] + dy*dy*sy[i]));
            bool fg  = (iv == i+1);
            float v  = fg ? (1.f - d) : d;              // e = 2v
            int bin  = min((int)(v * (float)NBINS), NBINS-1);
            atomicAdd(hb + i*(NBINS*2) + bin*2 + (fg?1:0), 1u);
            float df = P.z - d;
            sfg[i] += fg ? df*df : 0.f;
        }
    }
    // reduce sfg[7] across block
    __shared__ float sred[NID][8];
    int lane = threadIdx.x & 31;
    #pragma unroll
    for (int i = 0; i < NID; i++) {
        float s = sfg[i];
        #pragma unroll
        for (int o = 16; o; o >>= 1) s += __shfl_down_sync(FULLM, s, o);
        if (lane == 0) sred[i][threadIdx.x >> 5] = s;
    }
    __syncthreads();
    if (threadIdx.x < NID) {
        float s = 0.f;
        #pragma unroll
        for (int w = 0; w < 8; w++) s += sred[threadIdx.x][w];
        atomicAdd(&g_seedfg[b*NID + threadIdx.x], s);
    }
}

// ---------------- stage D: Lovász via descending-bin scan (fp32) ----------------
__global__ __launch_bounds__(256) void stageD() {
    int t = blockIdx.x;
    if (g_task[t*8+5] == 0.f) { if (threadIdx.x == 0) g_instl[t] = 0.f; return; }
    const uint2* hh = (const uint2*)(g_hist + t*(NBINS*2));   // .x=bg .y=fg
    int tid = threadIdx.x;
    const int BPT = NBINS/256;    // 8 bins/thread, contiguous descending chunk
    int hi = NBINS-1 - tid*BPT;

    unsigned lf = 0, lt = 0;
    #pragma unroll
    for (int j = 0; j < BPT; j++) {
        uint2 c = hh[hi - j];
        lf += c.y; lt += c.x + c.y;
    }

    __shared__ unsigned sWF[8], sWT[8];
    int lane = tid & 31, warp = tid >> 5;
    unsigned incF = lf, incT = lt;
    #pragma unroll
    for (int o = 1; o < 32; o <<= 1) {
        unsigned vF = __shfl_up_sync(FULLM, incF, o);
        unsigned vT = __shfl_up_sync(FULLM, incT, o);
        if (lane >= o) { incF += vF; incT += vT; }
    }
    if (lane == 31) { sWF[warp] = incF; sWT[warp] = incT; }
    __syncthreads();
    if (warp == 0 && lane < 8) {
        unsigned aF = sWF[lane], aT = sWT[lane];
        #pragma unroll
        for (int o = 1; o < 8; o <<= 1) {
            unsigned vF = __shfl_up_sync(0xffu, aF, o);
            unsigned vT = __shfl_up_sync(0xffu, aT, o);
            if (lane >= o) { aF += vF; aT += vT; }
        }
        sWF[lane] = aF; sWT[lane] = aT;
    }
    __syncthreads();
    unsigned F = (warp ? sWF[warp-1] : 0u) + incF - lf;
    unsigned T = (warp ? sWT[warp-1] : 0u) + incT - lt;

    float G = (float)sWF[7];      // exact fg total (< 2^24)
    float jprev = 1.f - (G - (float)F) / (G + (float)(T - F));
    float loss = 0.f;
    #pragma unroll
    for (int j = 0; j < BPT; j++) {
        int bin = hi - j;
        uint2 cc = hh[bin];
        unsigned a = cc.y, c = cc.x + cc.y;
        if (c) {
            F += a; T += c;
            float jnew = 1.f - (G - (float)F) / (G + (float)(T - F));
            float e = ((float)bin + 0.5f) * (2.0f/(float)NBINS);
            loss += e * (jnew - jprev);
            jprev = jnew;
        }
    }
    #pragma unroll
    for (int o = 16; o; o >>= 1) loss += __shfl_down_sync(FULLM, loss, o);
    __shared__ float sL[8];
    if (lane == 0) sL[warp] = loss;
    __syncthreads();
    if (tid == 0) {
        float v = 0.f;
        #pragma unroll
        for (int w = 0; w < 8; w++) v += sL[w];
        g_instl[t] = v;
    }
}

// ---------------- final combine ----------------
__global__ void combineK(float* __restrict__ out) {
    if (threadIdx.x != 0) return;
    float total = 0.f;
    for (int b = 0; b < BB; b++) {
        float ps = 0.f, il = 0.f, vl = 0.f, sf = 0.f;
        for (int i = 0; i < NID; i++) {
            int t = b*NID + i;
            float p = g_task[t*8+5];
            ps += p;
            il += g_instl[t]    * p;
            vl += g_task[t*8+4] * p;
            sf += g_seedfg[t]   * p;
        }
        float obj = fmaxf(ps, 1.f);
        float seed_loss = (g_batch[b*3+2] + 200.f*sf) / (float)HW;
        float loss_b = il/obj + 10.f*(vl/obj) + seed_loss;
        float cls_b  = g_batch[b*3+0] / fmaxf(g_batch[b*3+1], 1.f);
        total += loss_b + cls_b;
    }
    out[0] = total * 0.25f;
}

extern "C" void kernel_launch(void* const* d_in, const int* in_sizes, int n_in,
                              void* d_out, int out_size) {
    const float* pred = (const float*)d_in[0];
    const int*   inst = (const int*)  d_in[1];
    const int*   lab  = (const int*)  d_in[2];
    float* out = (float*)d_out;

    zeroK   <<<64, 256>>>();
    stageA  <<<dim3(HW/2048, BB), 256>>>(pred, inst, lab);
    stageB  <<<1, 32>>>();
    stageC  <<<dim3(HW/2048, BB), 256>>>();
    stageD  <<<NTASK, 256>>>();
    combineK<<<1, 32>>>(out);
}